// round 13
// baseline (speedup 1.0000x reference)
#include <cuda_runtime.h>
#include <cuda_bf16.h>
#include <cstdint>

// Problem constants (fixed shapes): B=4, C=64, H=W=128, O=64, K=3
#define BB 4
#define CC 64
#define HH 128
#define WW 128
#define OO 64
#define HWP (HH*WW)          // 16384
#define NPIX (BB*HWP)        // 65536
#define TILE 128             // pixels per k_main block
#define NBLK (NPIX / TILE)   // 512
#define BPITCH 144           // smem row pitch bytes (72 bf16): 144/16=9 -> conflict-free ldmatrix

typedef unsigned long long u64;
typedef unsigned int u32;

// ---------------- scratch (static device globals; no allocation) ----------------
__device__ float  g_xh[(size_t)NPIX * CC];       // x in NHWC: [b][h][w][c]   16 MB
__device__ float4 g_smp[(size_t)9 * NPIX];       // per (tap, pixel): ys, xs, mask
__device__ float  g_raw[(size_t)NPIX * OO];      // pre-BN conv output, [pix][o]
__device__ __align__(16) unsigned char g_wth[9 * OO * BPITCH];  // weight hi bf16 [tap][o][c] pitched
__device__ __align__(16) unsigned char g_wtl[9 * OO * BPITCH];  // weight lo bf16
__device__ float  g_owt[576 * 28];               // offset weights, [c*9+kk][oc(pad to 28)]
__device__ float  g_psum[NBLK * OO];             // BN partial sums (per k_main block)
__device__ float  g_psq[NBLK * OO];              // BN partial sumsq
__device__ float  g_scale[OO];
__device__ float  g_shift[OO];

// ---------------- packed f32x2 helpers (Blackwell FFMA2) ----------------
__device__ __forceinline__ void ffma2(u64& c, u64 a, u64 b) {
    asm("fma.rn.f32x2 %0, %1, %2, %0;" : "+l"(c) : "l"(a), "l"(b));
}
__device__ __forceinline__ u64 pack2(float v) {
    u64 r; asm("mov.b64 %0, {%1, %1};" : "=l"(r) : "f"(v)); return r;
}
__device__ __forceinline__ u64 pack2f(float a, float b) {
    u64 r; asm("mov.b64 %0, {%1, %2};" : "=l"(r) : "f"(a), "f"(b)); return r;
}
__device__ __forceinline__ float2 unpack2(u64 v) {
    float2 f; asm("mov.b64 {%0, %1}, %2;" : "=f"(f.x), "=f"(f.y) : "l"(v)); return f;
}

// ---------------- mma/ldmatrix helpers (baseline PTX, works on sm_100) ----------------
__device__ __forceinline__ u32 smem_u32(const void* p) {
    u32 a;
    asm("{ .reg .u64 t; cvta.to.shared.u64 t, %1; cvt.u32.u64 %0, t; }" : "=r"(a) : "l"(p));
    return a;
}
__device__ __forceinline__ void ldsm4(u32* r, u32 addr) {
    asm volatile("ldmatrix.sync.aligned.m8n8.x4.shared.b16 {%0,%1,%2,%3}, [%4];"
        : "=r"(r[0]), "=r"(r[1]), "=r"(r[2]), "=r"(r[3]) : "r"(addr));
}
__device__ __forceinline__ void mma16816(float* c, const u32* a, u32 b0, u32 b1) {
    asm volatile(
        "mma.sync.aligned.m16n8k16.row.col.f32.bf16.bf16.f32 "
        "{%0,%1,%2,%3}, {%4,%5,%6,%7}, {%8,%9}, {%0,%1,%2,%3};"
        : "+f"(c[0]), "+f"(c[1]), "+f"(c[2]), "+f"(c[3])
        : "r"(a[0]), "r"(a[1]), "r"(a[2]), "r"(a[3]), "r"(b0), "r"(b1));
}

// k_main smem layout (single buffer; 3 CTAs/SM)
#define SMA_H 0
#define SMA_L (TILE * BPITCH)                  // 18432
#define SMB_H (2 * TILE * BPITCH)              // 36864
#define SMB_L (SMB_H + OO * BPITCH)            // 46080
#define SM_TOT (SMB_L + OO * BPITCH)           // 55296

// ---------------- K0: NCHW -> NHWC transpose ----------------
__global__ void k_transpose(const float* __restrict__ x) {
    __shared__ float t[32][33];
    int b  = blockIdx.z;
    int c0 = blockIdx.y * 32;
    int p0 = blockIdx.x * 32;
    int tx = threadIdx.x, ty = threadIdx.y;
    #pragma unroll
    for (int j = 0; j < 4; j++) {
        int c = c0 + ty + j * 8;
        t[ty + j * 8][tx] = x[((size_t)(b * CC + c)) * HWP + p0 + tx];
    }
    __syncthreads();
    #pragma unroll
    for (int j = 0; j < 4; j++) {
        int p = p0 + ty + j * 8;
        g_xh[((size_t)(b * HWP + p)) * CC + c0 + tx] = t[tx][ty + j * 8];
    }
}

// ---------------- Kprep: weight relayouts (bf16 hi/lo split, pitched) ----------------
__global__ void k_prep(const float* __restrict__ wmain, const float* __restrict__ ow) {
    int i = blockIdx.x * 256 + threadIdx.x;
    if (i < 9 * OO * CC) {
        int k = i >> 12;           // tap
        int r = i & 4095;
        int o = r >> 6, c = r & 63;
        float w = wmain[o * 576 + c * 9 + k];
        __nv_bfloat16 hi = __float2bfloat16_rn(w);
        float lo = w - __bfloat162float(hi);
        __nv_bfloat16 lob = __float2bfloat16_rn(lo);
        size_t off = (size_t)k * OO * BPITCH + o * BPITCH + c * 2;
        *(__nv_bfloat16*)(g_wth + off) = hi;
        *(__nv_bfloat16*)(g_wtl + off) = lob;
    }
    if (i < 576 * 28) {
        int t = i / 28, oc = i % 28;            // t = c*9 + kk
        g_owt[i] = (oc < 27) ? ow[oc * 576 + t] : 0.0f;
    }
}

// ---------------- K1: offset conv -> sample coords + mask (FFMA2) ----------------
__global__ __launch_bounds__(128) void k_offset(const float* __restrict__ ob) {
    extern __shared__ float ws[];   // [576][28]
    int blk = blockIdx.x;           // 0..255
    int t = threadIdx.x;
    int b = blk >> 6;
    int h = ((blk & 63) << 1) + (t >> 6);
    int w0 = (t & 63) << 1;

    for (int i = t; i < 576 * 28; i += 128) ws[i] = g_owt[i];
    __syncthreads();

    u64 acc[28];
    #pragma unroll
    for (int j = 0; j < 14; j++) {
        float lo = (2 * j < 27) ? ob[2 * j] : 0.0f;
        float hi = (2 * j + 1 < 27) ? ob[2 * j + 1] : 0.0f;
        u64 v = pack2f(lo, hi);
        acc[j] = v; acc[14 + j] = v;
    }

    const float* xb = g_xh + (size_t)(b << 14) * CC;

    #pragma unroll 1
    for (int c4 = 0; c4 < 16; c4++) {
        float4 tap[3][4];
        #pragma unroll
        for (int dy = 0; dy < 3; dy++)
        #pragma unroll
        for (int dx = 0; dx < 4; dx++) {
            int y = h + dy - 1, x = w0 + dx - 1;
            bool v = ((unsigned)y < 128u) && ((unsigned)x < 128u);
            tap[dy][dx] = v ? *(const float4*)(xb + ((y << 7) + x) * CC + c4 * 4)
                            : make_float4(0.f, 0.f, 0.f, 0.f);
        }
        #pragma unroll
        for (int j = 0; j < 4; j++) {
            int cc = c4 * 4 + j;
            #pragma unroll
            for (int kk = 0; kk < 9; kk++) {
                int dy = kk / 3, dx = kk % 3;
                float4 t0 = tap[dy][dx], t1 = tap[dy][dx + 1];
                float v0 = (j == 0) ? t0.x : (j == 1) ? t0.y : (j == 2) ? t0.z : t0.w;
                float v1 = (j == 0) ? t1.x : (j == 1) ? t1.y : (j == 2) ? t1.z : t1.w;
                u64 vv0 = pack2(v0), vv1 = pack2(v1);
                const ulonglong2* wr = (const ulonglong2*)&ws[(cc * 9 + kk) * 28];
                #pragma unroll
                for (int q = 0; q < 7; q++) {
                    ulonglong2 wq = wr[q];
                    ffma2(acc[2 * q],          vv0, wq.x);
                    ffma2(acc[2 * q + 1],      vv0, wq.y);
                    ffma2(acc[14 + 2 * q],     vv1, wq.x);
                    ffma2(acc[14 + 2 * q + 1], vv1, wq.y);
                }
            }
        }
    }

    float a0[28], a1[28];
    #pragma unroll
    for (int j = 0; j < 14; j++) {
        float2 f = unpack2(acc[j]);       a0[2 * j] = f.x; a0[2 * j + 1] = f.y;
        float2 g = unpack2(acc[14 + j]);  a1[2 * j] = g.x; a1[2 * j + 1] = g.y;
    }
    int pix = (b << 14) + (h << 7) + w0;
    #pragma unroll
    for (int k = 0; k < 9; k++) {
        float by = (float)(h - 1) + (float)(k / 3);
        float bx0 = (float)(w0 - 1) + (float)(k % 3);
        float m0 = 1.0f / (1.0f + expf(-a0[18 + k]));
        float m1 = 1.0f / (1.0f + expf(-a1[18 + k]));
        g_smp[(size_t)k * NPIX + pix]     = make_float4(by + a0[2 * k], bx0 + a0[2 * k + 1], m0, 0.0f);
        g_smp[(size_t)k * NPIX + pix + 1] = make_float4(by + a1[2 * k], bx0 + 1.0f + a1[2 * k + 1], m1, 0.0f);
    }
}

// ---------------- K2: gather + mma.sync (single buffer, 3 CTAs/SM) + fused BN stats ----------------
__global__ __launch_bounds__(256, 3) void k_main() {
    extern __shared__ __align__(16) char smc[];
    u32 sb = smem_u32(smc);

    int t = threadIdx.x;
    int w = t >> 5, lane = t & 31;
    int pix0 = blockIdx.x * TILE;
    int b = pix0 >> 14;
    const float* xb = g_xh + (size_t)(b << 14) * CC;

    int gg = t >> 3;   // gather group 0..31 -> pixels 4gg..4gg+3
    int j  = t & 7;    // lane in group -> channels 4j..4j+3 and 32+4j..32+4j+3

    int mb = (w & 3) * 32;    // warp m base (pixels)
    int nb = (w >> 2) * 32;   // warp n base (outputs)

    float acc[2][4][4];
    #pragma unroll
    for (int mi = 0; mi < 2; mi++)
        #pragma unroll
        for (int ni = 0; ni < 4; ni++)
            #pragma unroll
            for (int q = 0; q < 4; q++) acc[mi][ni][q] = 0.0f;

    // ldmatrix addresses (constant per thread across taps)
    u32 aAddr[2];
    #pragma unroll
    for (int mi = 0; mi < 2; mi++)
        aAddr[mi] = sb + SMA_H + (mb + 16 * mi + (lane & 15)) * BPITCH + (lane >> 4) * 16;
    u32 bAddr[2];
    #pragma unroll
    for (int half = 0; half < 2; half++) {
        int nrow = nb + 16 * half + ((lane >> 4) & 1) * 8 + (lane & 7);
        bAddr[half] = sb + SMB_H + nrow * BPITCH + ((lane >> 3) & 1) * 16;
    }

    #pragma unroll 1
    for (int k = 0; k < 9; k++) {
        __syncthreads();   // previous GEMM finished reading smem

        // --- B tiles: copy 9216B hi + 9216B lo (uint4, coalesced) ---
        {
            const uint4* sh = (const uint4*)(g_wth + (size_t)k * OO * BPITCH);
            const uint4* sl = (const uint4*)(g_wtl + (size_t)k * OO * BPITCH);
            uint4* dh = (uint4*)(smc + SMB_H);
            uint4* dl = (uint4*)(smc + SMB_L);
            dh[t] = sh[t]; dl[t] = sl[t];
            dh[t + 256] = sh[t + 256]; dl[t + 256] = sl[t + 256];
            if (t < 64) { dh[t + 512] = sh[t + 512]; dl[t + 512] = sl[t + 512]; }
        }

        // --- A tiles: cooperative bilinear gather + bf16 hi/lo split ---
        #pragma unroll 1
        for (int s = 0; s < 4; s++) {
            int p = gg * 4 + s;
            float4 sp = g_smp[(size_t)k * NPIX + pix0 + p];
            float y0f = floorf(sp.x), x0f = floorf(sp.y);
            float fy = sp.x - y0f, fx = sp.y - x0f;
            int y0 = (int)y0f, x0 = (int)x0f;
            float m = sp.z, gy = 1.0f - fy, gx = 1.0f - fx;
            bool vy0 = ((unsigned)y0 < 128u), vy1 = ((unsigned)(y0 + 1) < 128u);
            bool vx0 = ((unsigned)x0 < 128u), vx1 = ((unsigned)(x0 + 1) < 128u);
            float w00 = (vy0 && vx0) ? gy * gx * m : 0.0f;
            float w01 = (vy0 && vx1) ? gy * fx * m : 0.0f;
            float w10 = (vy1 && vx0) ? fy * gx * m : 0.0f;
            float w11 = (vy1 && vx1) ? fy * fx * m : 0.0f;
            int r0 = (vy0 ? y0 : 0) << 7, r1 = (vy1 ? (y0 + 1) : 0) << 7;
            int cA = vx0 ? x0 : 0, cBx = vx1 ? (x0 + 1) : 0;
            const float* p00 = xb + (r0 + cA) * CC + 4 * j;
            const float* p01 = xb + (r0 + cBx) * CC + 4 * j;
            const float* p10 = xb + (r1 + cA) * CC + 4 * j;
            const float* p11 = xb + (r1 + cBx) * CC + 4 * j;
            float4 a00 = *(const float4*)p00, a01 = *(const float4*)p01;
            float4 a10 = *(const float4*)p10, a11 = *(const float4*)p11;
            float4 b00 = *(const float4*)(p00 + 32), b01 = *(const float4*)(p01 + 32);
            float4 b10 = *(const float4*)(p10 + 32), b11 = *(const float4*)(p11 + 32);

            float4 V0, V1;
            V0.x = fmaf(w00, a00.x, fmaf(w01, a01.x, fmaf(w10, a10.x, w11 * a11.x)));
            V0.y = fmaf(w00, a00.y, fmaf(w01, a01.y, fmaf(w10, a10.y, w11 * a11.y)));
            V0.z = fmaf(w00, a00.z, fmaf(w01, a01.z, fmaf(w10, a10.z, w11 * a11.z)));
            V0.w = fmaf(w00, a00.w, fmaf(w01, a01.w, fmaf(w10, a10.w, w11 * a11.w)));
            V1.x = fmaf(w00, b00.x, fmaf(w01, b01.x, fmaf(w10, b10.x, w11 * b11.x)));
            V1.y = fmaf(w00, b00.y, fmaf(w01, b01.y, fmaf(w10, b10.y, w11 * b11.y)));
            V1.z = fmaf(w00, b00.z, fmaf(w01, b01.z, fmaf(w10, b10.z, w11 * b11.z)));
            V1.w = fmaf(w00, b00.w, fmaf(w01, b01.w, fmaf(w10, b10.w, w11 * b11.w)));

            float vf[8] = {V0.x, V0.y, V0.z, V0.w, V1.x, V1.y, V1.z, V1.w};
            u32 hp[4], lp[4];
            #pragma unroll
            for (int q = 0; q < 4; q++) {
                __nv_bfloat16 h0 = __float2bfloat16_rn(vf[2 * q]);
                __nv_bfloat16 h1 = __float2bfloat16_rn(vf[2 * q + 1]);
                float l0 = vf[2 * q]     - __bfloat162float(h0);
                float l1 = vf[2 * q + 1] - __bfloat162float(h1);
                __nv_bfloat162 hh; hh.x = h0; hh.y = h1;
                __nv_bfloat162 ll = __floats2bfloat162_rn(l0, l1);
                memcpy(&hp[q], &hh, 4);
                memcpy(&lp[q], &ll, 4);
            }
            char* rowH = smc + SMA_H + p * BPITCH;
            char* rowL = smc + SMA_L + p * BPITCH;
            *(uint2*)(rowH + 8 * j)      = make_uint2(hp[0], hp[1]);
            *(uint2*)(rowH + 64 + 8 * j) = make_uint2(hp[2], hp[3]);
            *(uint2*)(rowL + 8 * j)      = make_uint2(lp[0], lp[1]);
            *(uint2*)(rowL + 64 + 8 * j) = make_uint2(lp[2], lp[3]);
        }
        __syncthreads();

        // --- GEMM: 4 k16 steps ---
        #pragma unroll
        for (int ks = 0; ks < 4; ks++) {
            u32 ah[2][4], al[2][4];
            #pragma unroll
            for (int mi = 0; mi < 2; mi++) {
                ldsm4(ah[mi], aAddr[mi] + ks * 32);
                ldsm4(al[mi], aAddr[mi] + ks * 32 + (SMA_L - SMA_H));
            }
            #pragma unroll
            for (int half = 0; half < 2; half++) {
                u32 bh[4], bl[4];
                ldsm4(bh, bAddr[half] + ks * 32);
                ldsm4(bl, bAddr[half] + ks * 32 + (SMB_L - SMB_H));
                #pragma unroll
                for (int mi = 0; mi < 2; mi++) {
                    mma16816(acc[mi][2 * half],     ah[mi], bh[0], bh[1]);
                    mma16816(acc[mi][2 * half],     ah[mi], bl[0], bl[1]);
                    mma16816(acc[mi][2 * half],     al[mi], bh[0], bh[1]);
                    mma16816(acc[mi][2 * half + 1], ah[mi], bh[2], bh[3]);
                    mma16816(acc[mi][2 * half + 1], ah[mi], bl[2], bl[3]);
                    mma16816(acc[mi][2 * half + 1], al[mi], bh[2], bh[3]);
                }
            }
        }
    }
    __syncthreads();   // all GEMM smem reads complete before stats reuse smem

    // ---- epilogue: fragment -> g_raw ----
    int er = lane >> 2, ec = (lane & 3) * 2;
    #pragma unroll
    for (int mi = 0; mi < 2; mi++) {
        #pragma unroll
        for (int ni = 0; ni < 4; ni++) {
            int pix = pix0 + mb + 16 * mi + er;
            int o = nb + 8 * ni + ec;
            *(float2*)(g_raw + (size_t)pix * OO + o)       = make_float2(acc[mi][ni][0], acc[mi][ni][1]);
            *(float2*)(g_raw + (size_t)(pix + 8) * OO + o) = make_float2(acc[mi][ni][2], acc[mi][ni][3]);
        }
    }

    // ---- fused BN partial stats (fixed-order shfl tree + fixed warp order) ----
    float ps[8], pq[8];
    #pragma unroll
    for (int ni = 0; ni < 4; ni++) {
        float s0 = 0.f, q0 = 0.f, s1 = 0.f, q1 = 0.f;
        #pragma unroll
        for (int mi = 0; mi < 2; mi++) {
            float a0 = acc[mi][ni][0], a1 = acc[mi][ni][1];
            float a2 = acc[mi][ni][2], a3 = acc[mi][ni][3];
            s0 += a0 + a2;  q0 += a0 * a0 + a2 * a2;
            s1 += a1 + a3;  q1 += a1 * a1 + a3 * a3;
        }
        ps[2 * ni] = s0; pq[2 * ni] = q0;
        ps[2 * ni + 1] = s1; pq[2 * ni + 1] = q1;
    }
    #pragma unroll
    for (int off = 4; off <= 16; off <<= 1) {
        #pragma unroll
        for (int i = 0; i < 8; i++) {
            ps[i] += __shfl_xor_sync(0xFFFFFFFF, ps[i], off);
            pq[i] += __shfl_xor_sync(0xFFFFFFFF, pq[i], off);
        }
    }
    float* sms = (float*)smc;          // [8][32]
    float* smq = sms + 256;            // [8][32]
    if (lane < 4) {
        #pragma unroll
        for (int ni = 0; ni < 4; ni++) {
            int lo = 8 * ni + lane * 2;
            sms[w * 32 + lo]     = ps[2 * ni];
            sms[w * 32 + lo + 1] = ps[2 * ni + 1];
            smq[w * 32 + lo]     = pq[2 * ni];
            smq[w * 32 + lo + 1] = pq[2 * ni + 1];
        }
    }
    __syncthreads();
    if (t < 64) {
        int grp = t >> 5, wo = t & 31;
        float S = sms[(grp * 4 + 0) * 32 + wo] + sms[(grp * 4 + 1) * 32 + wo]
                + sms[(grp * 4 + 2) * 32 + wo] + sms[(grp * 4 + 3) * 32 + wo];
        float Q = smq[(grp * 4 + 0) * 32 + wo] + smq[(grp * 4 + 1) * 32 + wo]
                + smq[(grp * 4 + 2) * 32 + wo] + smq[(grp * 4 + 3) * 32 + wo];
        g_psum[blockIdx.x * OO + t] = S;
        g_psq[blockIdx.x * OO + t]  = Q;
    }
}

// ---------------- K3: finalize stats -> scale/shift ----------------
__global__ void k_stats2(const float* __restrict__ gamma, const float* __restrict__ beta) {
    __shared__ float ss[256], sq[256];
    int ch = blockIdx.x, t = threadIdx.x;
    ss[t] = g_psum[t * OO + ch] + g_psum[(t + 256) * OO + ch];
    sq[t] = g_psq[t * OO + ch]  + g_psq[(t + 256) * OO + ch];
    __syncthreads();
    for (int s = 128; s > 0; s >>= 1) {
        if (t < s) { ss[t] += ss[t + s]; sq[t] += sq[t + s]; }
        __syncthreads();
    }
    if (t == 0) {
        const float inv_n = 1.0f / (float)NPIX;
        float mean = ss[0] * inv_n;
        float var  = sq[0] * inv_n - mean * mean;
        float inv  = rsqrtf(var + 1e-5f);
        float sc   = gamma[ch] * inv;
        g_scale[ch] = sc;
        g_shift[ch] = beta[ch] - mean * sc;
        // conv bias cancels exactly inside batch-norm (per-channel constant)
    }
}

// ---------------- K4: BN + ReLU + NHWC->NCHW ----------------
__global__ void k_bnout(float* __restrict__ out) {
    __shared__ float s[64][65];
    __shared__ float scs[64], shs[64];
    int t = threadIdx.x;
    if (t < 64) { scs[t] = g_scale[t]; shs[t] = g_shift[t]; }
    __syncthreads();
    int pix0 = blockIdx.x * 64;
    int b = pix0 >> 14;
    int pl = pix0 & 16383;
    #pragma unroll
    for (int j = 0; j < 4; j++) {
        int idx = t + j * 256;
        int p = idx >> 4;      // 0..63 local pixel
        int q = idx & 15;      // float4 group of channels
        float4 v = *(const float4*)(g_raw + (size_t)(pix0 + p) * OO + q * 4);
        int c = q * 4;
        s[c + 0][p] = fmaxf(fmaf(v.x, scs[c + 0], shs[c + 0]), 0.0f);
        s[c + 1][p] = fmaxf(fmaf(v.y, scs[c + 1], shs[c + 1]), 0.0f);
        s[c + 2][p] = fmaxf(fmaf(v.z, scs[c + 2], shs[c + 2]), 0.0f);
        s[c + 3][p] = fmaxf(fmaf(v.w, scs[c + 3], shs[c + 3]), 0.0f);
    }
    __syncthreads();
    #pragma unroll
    for (int j = 0; j < 4; j++) {
        int idx = t + j * 256;
        int o = idx >> 4;
        int q = idx & 15;
        float4 r = make_float4(s[o][q * 4], s[o][q * 4 + 1], s[o][q * 4 + 2], s[o][q * 4 + 3]);
        *(float4*)(out + (size_t)(b * OO + o) * HWP + pl + q * 4) = r;
    }
}

// ---------------- launch ----------------
extern "C" void kernel_launch(void* const* d_in, const int* in_sizes, int n_in,
                              void* d_out, int out_size) {
    const float* x     = (const float*)d_in[0];
    const float* ow    = (const float*)d_in[1];
    const float* ob    = (const float*)d_in[2];
    const float* wt    = (const float*)d_in[3];
    // d_in[4] = bias: cancels exactly in batch norm, unused
    const float* gamma = (const float*)d_in[5];
    const float* beta  = (const float*)d_in[6];
    float* out = (float*)d_out;

    cudaFuncSetAttribute(k_offset, cudaFuncAttributeMaxDynamicSharedMemorySize, 576 * 28 * 4);
    cudaFuncSetAttribute(k_main, cudaFuncAttributeMaxDynamicSharedMemorySize, SM_TOT);

    k_transpose<<<dim3(HWP / 32, CC / 32, BB), dim3(32, 8)>>>(x);
    k_prep<<<(9 * OO * CC + 255) / 256, 256>>>(wt, ow);
    k_offset<<<BB * HH / 2, 128, 576 * 28 * 4>>>(ob);
    k_main<<<NBLK, 256, SM_TOT>>>();
    k_stats2<<<64, 256>>>(gamma, beta);
    k_bnout<<<NPIX / 64, 256>>>(out);
}

// round 14
// speedup vs baseline: 1.3475x; 1.3475x over previous
#include <cuda_runtime.h>
#include <cuda_bf16.h>
#include <cstdint>

// Problem constants (fixed shapes): B=4, C=64, H=W=128, O=64, K=3
#define BB 4
#define CC 64
#define HH 128
#define WW 128
#define OO 64
#define HWP (HH*WW)          // 16384
#define NPIX (BB*HWP)        // 65536
#define TILE 128             // pixels per block (one image row)
#define NBLK (NPIX / TILE)   // 512
#define BPITCH 144           // smem row pitch bytes (72 bf16): conflict-free ldmatrix

typedef unsigned long long u64;
typedef unsigned int u32;

// ---------------- scratch (static device globals; no allocation) ----------------
__device__ float  g_xh[(size_t)NPIX * CC];       // x in NHWC: [b][h][w][c]   16 MB
__device__ float4 g_smp[(size_t)9 * NPIX];       // per (tap, pixel): ys, xs, mask
__device__ float  g_raw[(size_t)NPIX * OO];      // pre-BN conv output, [pix][o]
__device__ __align__(16) unsigned char g_wth[9 * OO * BPITCH];   // main weight hi bf16 [tap][o][c]
__device__ __align__(16) unsigned char g_wtl[9 * OO * BPITCH];   // main weight lo bf16
__device__ __align__(16) unsigned char g_owth[9 * 32 * BPITCH];  // offset weight hi bf16 [tap][n][c]
__device__ __align__(16) unsigned char g_owtl[9 * 32 * BPITCH];  // offset weight lo bf16
__device__ float  g_psum[NBLK * OO];             // BN partial sums (per k_main block)
__device__ float  g_psq[NBLK * OO];              // BN partial sumsq
__device__ float  g_scale[OO];
__device__ float  g_shift[OO];

// ---------------- mma/ldmatrix helpers (baseline PTX, works on sm_100) ----------------
__device__ __forceinline__ u32 smem_u32(const void* p) {
    u32 a;
    asm("{ .reg .u64 t; cvta.to.shared.u64 t, %1; cvt.u32.u64 %0, t; }" : "=r"(a) : "l"(p));
    return a;
}
__device__ __forceinline__ void ldsm4(u32* r, u32 addr) {
    asm volatile("ldmatrix.sync.aligned.m8n8.x4.shared.b16 {%0,%1,%2,%3}, [%4];"
        : "=r"(r[0]), "=r"(r[1]), "=r"(r[2]), "=r"(r[3]) : "r"(addr));
}
__device__ __forceinline__ void mma16816(float* c, const u32* a, u32 b0, u32 b1) {
    asm volatile(
        "mma.sync.aligned.m16n8k16.row.col.f32.bf16.bf16.f32 "
        "{%0,%1,%2,%3}, {%4,%5,%6,%7}, {%8,%9}, {%0,%1,%2,%3};"
        : "+f"(c[0]), "+f"(c[1]), "+f"(c[2]), "+f"(c[3])
        : "r"(a[0]), "r"(a[1]), "r"(a[2]), "r"(a[3]), "r"(b0), "r"(b1));
}
// split a float4 pair (8 ch) into bf16 hi/lo words and store to pitched rows
__device__ __forceinline__ void splitStore(float4 V0, float4 V1, char* rowH, char* rowL, int j) {
    float vf[8] = {V0.x, V0.y, V0.z, V0.w, V1.x, V1.y, V1.z, V1.w};
    u32 hp[4], lp[4];
    #pragma unroll
    for (int q = 0; q < 4; q++) {
        __nv_bfloat16 h0 = __float2bfloat16_rn(vf[2 * q]);
        __nv_bfloat16 h1 = __float2bfloat16_rn(vf[2 * q + 1]);
        float l0 = vf[2 * q]     - __bfloat162float(h0);
        float l1 = vf[2 * q + 1] - __bfloat162float(h1);
        __nv_bfloat162 hh; hh.x = h0; hh.y = h1;
        __nv_bfloat162 ll = __floats2bfloat162_rn(l0, l1);
        memcpy(&hp[q], &hh, 4);
        memcpy(&lp[q], &ll, 4);
    }
    *(uint2*)(rowH + 8 * j)      = make_uint2(hp[0], hp[1]);
    *(uint2*)(rowH + 64 + 8 * j) = make_uint2(hp[2], hp[3]);
    *(uint2*)(rowL + 8 * j)      = make_uint2(lp[0], lp[1]);
    *(uint2*)(rowL + 64 + 8 * j) = make_uint2(lp[2], lp[3]);
}

// k_main smem layout: double-buffered A hi/lo + B hi/lo (R11 pipelined config)
#define BUFSZ   55296
#define SMA_H(b) ((b) * BUFSZ + 0)
#define SMA_L(b) ((b) * BUFSZ + TILE * BPITCH)
#define SMB_H(b) ((b) * BUFSZ + 2 * TILE * BPITCH)
#define SMB_L(b) ((b) * BUFSZ + 2 * TILE * BPITCH + OO * BPITCH)
#define SM_TOT  (2 * BUFSZ)                                 // 110592

// k_offmma smem layout (single buffer)
#define OS_AH 0
#define OS_AL (TILE * BPITCH)            // 18432
#define OS_BH (2 * TILE * BPITCH)        // 36864
#define OS_BL (OS_BH + 32 * BPITCH)      // 41472
#define OS_TOT (OS_BL + 32 * BPITCH)     // 46080
#define CPITCH 34                        // epilogue C smem pitch (floats)

// ---------------- K0: NCHW -> NHWC transpose ----------------
__global__ void k_transpose(const float* __restrict__ x) {
    __shared__ float t[32][33];
    int b  = blockIdx.z;
    int c0 = blockIdx.y * 32;
    int p0 = blockIdx.x * 32;
    int tx = threadIdx.x, ty = threadIdx.y;
    #pragma unroll
    for (int j = 0; j < 4; j++) {
        int c = c0 + ty + j * 8;
        t[ty + j * 8][tx] = x[((size_t)(b * CC + c)) * HWP + p0 + tx];
    }
    __syncthreads();
    #pragma unroll
    for (int j = 0; j < 4; j++) {
        int p = p0 + ty + j * 8;
        g_xh[((size_t)(b * HWP + p)) * CC + c0 + tx] = t[tx][ty + j * 8];
    }
}

// ---------------- Kprep: weight relayouts (bf16 hi/lo split, pitched) ----------------
__global__ void k_prep(const float* __restrict__ wmain, const float* __restrict__ ow) {
    int i = blockIdx.x * 256 + threadIdx.x;
    if (i < 9 * OO * CC) {
        int k = i >> 12;           // tap
        int r = i & 4095;
        int o = r >> 6, c = r & 63;
        float w = wmain[o * 576 + c * 9 + k];
        __nv_bfloat16 hi = __float2bfloat16_rn(w);
        float lo = w - __bfloat162float(hi);
        size_t off = (size_t)k * OO * BPITCH + o * BPITCH + c * 2;
        *(__nv_bfloat16*)(g_wth + off) = hi;
        *(__nv_bfloat16*)(g_wtl + off) = __float2bfloat16_rn(lo);
    }
    if (i < 9 * 32 * CC) {         // offset conv weights: [tap][n(pad32)][c]
        int k = i >> 11;           // / 2048
        int r = i & 2047;
        int n = r >> 6, c = r & 63;
        float w = (n < 27) ? ow[n * 576 + c * 9 + k] : 0.0f;
        __nv_bfloat16 hi = __float2bfloat16_rn(w);
        float lo = w - __bfloat162float(hi);
        size_t off = (size_t)k * 32 * BPITCH + n * BPITCH + c * 2;
        *(__nv_bfloat16*)(g_owth + off) = hi;
        *(__nv_bfloat16*)(g_owtl + off) = __float2bfloat16_rn(lo);
    }
}

// ---------------- K1: offset conv via mma.sync -> sample coords + mask ----------------
// Block: 128 pixels = one image row, 256 threads (8 warps).
// M=128 pix, N=32 (27 used), K=64 per tap x 9 taps. bf16 hi/lo 3-term split.
__global__ __launch_bounds__(256, 3) void k_offmma(const float* __restrict__ ob) {
    extern __shared__ __align__(16) char smc[];
    u32 sb = smem_u32(smc);
    int t = threadIdx.x;
    int w = t >> 5, lane = t & 31;
    int pix0 = blockIdx.x * TILE;
    int b = pix0 >> 14;
    int h = (pix0 >> 7) & 127;
    const float* xb = g_xh + (size_t)(b << 14) * CC;

    int gg = t >> 3, j = t & 7;   // gather: group gg -> pixels 4gg..4gg+3, lane j -> ch 4j.. / 32+4j..
    int mb = (w & 3) * 32;        // warp m base (pixels)
    int nbh = (w >> 2) * 16;      // warp n base (outputs), 2 n-halves of 16

    float acc[2][2][4];
    #pragma unroll
    for (int mi = 0; mi < 2; mi++)
        #pragma unroll
        for (int ni = 0; ni < 2; ni++)
            #pragma unroll
            for (int q = 0; q < 4; q++) acc[mi][ni][q] = 0.0f;

    u32 aAddr[2];
    #pragma unroll
    for (int mi = 0; mi < 2; mi++)
        aAddr[mi] = sb + OS_AH + (mb + 16 * mi + (lane & 15)) * BPITCH + (lane >> 4) * 16;
    u32 bAddr;
    {
        int nrow = nbh + ((lane >> 4) & 1) * 8 + (lane & 7);
        bAddr = sb + OS_BH + nrow * BPITCH + ((lane >> 3) & 1) * 16;
    }

    #pragma unroll 1
    for (int k = 0; k < 9; k++) {
        __syncthreads();
        // --- B slice: 32 rows x 144B, hi + lo (288 uint4 each) ---
        {
            const uint4* sh = (const uint4*)(g_owth + (size_t)k * 32 * BPITCH);
            const uint4* sl = (const uint4*)(g_owtl + (size_t)k * 32 * BPITCH);
            uint4* dh = (uint4*)(smc + OS_BH);
            uint4* dl = (uint4*)(smc + OS_BL);
            if (t < 288 - 256) { dh[t + 256] = sh[t + 256]; dl[t + 256] = sl[t + 256]; }
            dh[t] = sh[t]; dl[t] = sl[t];
        }
        // --- A tile: plain zero-padded tap gather, bf16 hi/lo split ---
        int y = h + k / 3 - 1;
        bool vy = ((unsigned)y < 128u);
        #pragma unroll 1
        for (int s = 0; s < 4; s++) {
            int p = gg * 4 + s;
            int x = p + (k % 3) - 1;
            bool v = vy && ((unsigned)x < 128u);
            float4 A0 = make_float4(0.f, 0.f, 0.f, 0.f), A1 = A0;
            if (v) {
                const float* src = xb + ((y << 7) + x) * CC + 4 * j;
                A0 = *(const float4*)src;
                A1 = *(const float4*)(src + 32);
            }
            splitStore(A0, A1, smc + OS_AH + p * BPITCH, smc + OS_AL + p * BPITCH, j);
        }
        __syncthreads();

        // --- GEMM: 4 k16 steps ---
        #pragma unroll
        for (int ks = 0; ks < 4; ks++) {
            u32 ah[2][4], al[2][4];
            #pragma unroll
            for (int mi = 0; mi < 2; mi++) {
                ldsm4(ah[mi], aAddr[mi] + ks * 32);
                ldsm4(al[mi], aAddr[mi] + ks * 32 + (OS_AL - OS_AH));
            }
            u32 bh[4], bl[4];
            ldsm4(bh, bAddr + ks * 32);
            ldsm4(bl, bAddr + ks * 32 + (OS_BL - OS_BH));
            #pragma unroll
            for (int mi = 0; mi < 2; mi++) {
                mma16816(acc[mi][0], ah[mi], bh[0], bh[1]);
                mma16816(acc[mi][0], ah[mi], bl[0], bl[1]);
                mma16816(acc[mi][0], al[mi], bh[0], bh[1]);
                mma16816(acc[mi][1], ah[mi], bh[2], bh[3]);
                mma16816(acc[mi][1], ah[mi], bl[2], bl[3]);
                mma16816(acc[mi][1], al[mi], bh[2], bh[3]);
            }
        }
    }
    __syncthreads();

    // --- stage C through smem: Csm[128][CPITCH] floats ---
    float* Csm = (float*)smc;
    int er = lane >> 2, ec = (lane & 3) * 2;
    #pragma unroll
    for (int mi = 0; mi < 2; mi++) {
        #pragma unroll
        for (int ni = 0; ni < 2; ni++) {
            int row = mb + 16 * mi + er;
            int col = nbh + 8 * ni + ec;
            *(float2*)&Csm[row * CPITCH + col]       = make_float2(acc[mi][ni][0], acc[mi][ni][1]);
            *(float2*)&Csm[(row + 8) * CPITCH + col] = make_float2(acc[mi][ni][2], acc[mi][ni][3]);
        }
    }
    __syncthreads();

    // --- per-pixel epilogue: coords + sigmoid -> g_smp ---
    if (t < TILE) {
        int pix = pix0 + t;
        float c[27];
        #pragma unroll
        for (int i = 0; i < 27; i++) c[i] = Csm[t * CPITCH + i] + ob[i];
        #pragma unroll
        for (int k = 0; k < 9; k++) {
            float ys = (float)(h - 1 + k / 3) + c[2 * k];
            float xs = (float)(t - 1 + k % 3) + c[2 * k + 1];
            float mk = 1.0f / (1.0f + expf(-c[18 + k]));
            g_smp[(size_t)k * NPIX + pix] = make_float4(ys, xs, mk, 0.0f);
        }
    }
}

// ---------------- gather helpers for k_main ----------------
struct Pref {
    float4 a00, a01, a10, a11, b00, b01, b10, b11;
    float w00, w01, w10, w11;
};
__device__ __forceinline__ Pref issueGather(const float* xb, float4 sp, int j) {
    Pref P;
    float y0f = floorf(sp.x), x0f = floorf(sp.y);
    float fy = sp.x - y0f, fx = sp.y - x0f;
    int y0 = (int)y0f, x0 = (int)x0f;
    float m = sp.z, gy = 1.0f - fy, gx = 1.0f - fx;
    bool vy0 = ((unsigned)y0 < 128u), vy1 = ((unsigned)(y0 + 1) < 128u);
    bool vx0 = ((unsigned)x0 < 128u), vx1 = ((unsigned)(x0 + 1) < 128u);
    P.w00 = (vy0 && vx0) ? gy * gx * m : 0.0f;
    P.w01 = (vy0 && vx1) ? gy * fx * m : 0.0f;
    P.w10 = (vy1 && vx0) ? fy * gx * m : 0.0f;
    P.w11 = (vy1 && vx1) ? fy * fx * m : 0.0f;
    int r0 = (vy0 ? y0 : 0) << 7, r1 = (vy1 ? (y0 + 1) : 0) << 7;
    int cA = vx0 ? x0 : 0, cBx = vx1 ? (x0 + 1) : 0;
    const float* p00 = xb + (r0 + cA) * CC + 4 * j;
    const float* p01 = xb + (r0 + cBx) * CC + 4 * j;
    const float* p10 = xb + (r1 + cA) * CC + 4 * j;
    const float* p11 = xb + (r1 + cBx) * CC + 4 * j;
    P.a00 = *(const float4*)p00;        P.a01 = *(const float4*)p01;
    P.a10 = *(const float4*)p10;        P.a11 = *(const float4*)p11;
    P.b00 = *(const float4*)(p00 + 32); P.b01 = *(const float4*)(p01 + 32);
    P.b10 = *(const float4*)(p10 + 32); P.b11 = *(const float4*)(p11 + 32);
    return P;
}
__device__ __forceinline__ void retireGather(const Pref& P, char* rowH, char* rowL, int j) {
    float4 V0, V1;
    V0.x = fmaf(P.w00, P.a00.x, fmaf(P.w01, P.a01.x, fmaf(P.w10, P.a10.x, P.w11 * P.a11.x)));
    V0.y = fmaf(P.w00, P.a00.y, fmaf(P.w01, P.a01.y, fmaf(P.w10, P.a10.y, P.w11 * P.a11.y)));
    V0.z = fmaf(P.w00, P.a00.z, fmaf(P.w01, P.a01.z, fmaf(P.w10, P.a10.z, P.w11 * P.a11.z)));
    V0.w = fmaf(P.w00, P.a00.w, fmaf(P.w01, P.a01.w, fmaf(P.w10, P.a10.w, P.w11 * P.a11.w)));
    V1.x = fmaf(P.w00, P.b00.x, fmaf(P.w01, P.b01.x, fmaf(P.w10, P.b10.x, P.w11 * P.b11.x)));
    V1.y = fmaf(P.w00, P.b00.y, fmaf(P.w01, P.b01.y, fmaf(P.w10, P.b10.y, P.w11 * P.b11.y)));
    V1.z = fmaf(P.w00, P.b00.z, fmaf(P.w01, P.b01.z, fmaf(P.w10, P.b10.z, P.w11 * P.b11.z)));
    V1.w = fmaf(P.w00, P.b00.w, fmaf(P.w01, P.b01.w, fmaf(P.w10, P.b10.w, P.w11 * P.b11.w)));
    splitStore(V0, V1, rowH, rowL, j);
}

// ---------------- K2: gather + mma.sync, pipelined (1 sync/tap) + fused BN stats ----------------
__global__ __launch_bounds__(256, 2) void k_main() {
    extern __shared__ __align__(16) char smc[];
    u32 sb = smem_u32(smc);

    int t = threadIdx.x;
    int w = t >> 5, lane = t & 31;
    int pix0 = blockIdx.x * TILE;
    int b = pix0 >> 14;
    const float* xb = g_xh + (size_t)(b << 14) * CC;

    int gg = t >> 3;   // gather group 0..31 -> pixels 4gg..4gg+3
    int j  = t & 7;    // lane in group -> channels 4j..4j+3 and 32+4j..32+4j+3

    int mb = (w & 3) * 32;    // warp m base (pixels)
    int nb = (w >> 2) * 32;   // warp n base (outputs)

    float acc[2][4][4];
    #pragma unroll
    for (int mi = 0; mi < 2; mi++)
        #pragma unroll
        for (int ni = 0; ni < 4; ni++)
            #pragma unroll
            for (int q = 0; q < 4; q++) acc[mi][ni][q] = 0.0f;

    u32 aOff[2];
    #pragma unroll
    for (int mi = 0; mi < 2; mi++)
        aOff[mi] = (mb + 16 * mi + (lane & 15)) * BPITCH + (lane >> 4) * 16;
    u32 bOff[2];
    #pragma unroll
    for (int half = 0; half < 2; half++) {
        int nrow = nb + 16 * half + ((lane >> 4) & 1) * 8 + (lane & 7);
        bOff[half] = nrow * BPITCH + ((lane >> 3) & 1) * 16;
    }

    // ---- prologue: B0 copy + gather tap 0 into buf0 ----
    {
        const uint4* sh = (const uint4*)g_wth;
        const uint4* sl = (const uint4*)g_wtl;
        uint4* dh = (uint4*)(smc + SMB_H(0));
        uint4* dl = (uint4*)(smc + SMB_L(0));
        dh[t] = sh[t]; dl[t] = sl[t];
        dh[t + 256] = sh[t + 256]; dl[t + 256] = sl[t + 256];
        if (t < 64) { dh[t + 512] = sh[t + 512]; dl[t + 512] = sl[t + 512]; }
        #pragma unroll 1
        for (int s = 0; s < 4; s++) {
            int p = gg * 4 + s;
            float4 sp = g_smp[pix0 + p];
            Pref P = issueGather(xb, sp, j);
            retireGather(P, smc + SMA_H(0) + p * BPITCH, smc + SMA_L(0) + p * BPITCH, j);
        }
    }
    __syncthreads();

    // ---- pipelined main loop ----
    #pragma unroll 1
    for (int k = 0; k < 9; k++) {
        int cur = k & 1, nxt = cur ^ 1;
        bool pre = (k < 8);
        u32 baseAH = sb + SMA_H(cur), baseAL = sb + SMA_L(cur);
        u32 baseBH = sb + SMB_H(cur), baseBL = sb + SMB_L(cur);
        char* rowHb = smc + SMA_H(nxt);
        char* rowLb = smc + SMA_L(nxt);
        uint4 bhp0, blp0, bhp1, blp1, bhp2, blp2;

        #pragma unroll
        for (int s = 0; s < 4; s++) {
            // --- issue prefetch for tap k+1 ---
            Pref P;
            int p = gg * 4 + s;
            if (pre) {
                if (s == 0) {
                    const uint4* shh = (const uint4*)(g_wth + (size_t)(k + 1) * OO * BPITCH);
                    const uint4* sll = (const uint4*)(g_wtl + (size_t)(k + 1) * OO * BPITCH);
                    bhp0 = shh[t];       blp0 = sll[t];
                    bhp1 = shh[t + 256]; blp1 = sll[t + 256];
                    if (t < 64) { bhp2 = shh[t + 512]; blp2 = sll[t + 512]; }
                }
                float4 sp = g_smp[(size_t)(k + 1) * NPIX + pix0 + p];
                P = issueGather(xb, sp, j);
            }

            // --- GEMM step ks = s on current buffers ---
            {
                u32 ah[2][4], al[2][4];
                #pragma unroll
                for (int mi = 0; mi < 2; mi++) {
                    ldsm4(ah[mi], baseAH + aOff[mi] + s * 32);
                    ldsm4(al[mi], baseAL + aOff[mi] + s * 32);
                }
                #pragma unroll
                for (int half = 0; half < 2; half++) {
                    u32 bh[4], bl[4];
                    ldsm4(bh, baseBH + bOff[half] + s * 32);
                    ldsm4(bl, baseBL + bOff[half] + s * 32);
                    #pragma unroll
                    for (int mi = 0; mi < 2; mi++) {
                        mma16816(acc[mi][2 * half],     ah[mi], bh[0], bh[1]);
                        mma16816(acc[mi][2 * half],     ah[mi], bl[0], bl[1]);
                        mma16816(acc[mi][2 * half],     al[mi], bh[0], bh[1]);
                        mma16816(acc[mi][2 * half + 1], ah[mi], bh[2], bh[3]);
                        mma16816(acc[mi][2 * half + 1], ah[mi], bl[2], bl[3]);
                        mma16816(acc[mi][2 * half + 1], al[mi], bh[2], bh[3]);
                    }
                }
            }

            // --- retire prefetch into next buffers ---
            if (pre) {
                retireGather(P, rowHb + p * BPITCH, rowLb + p * BPITCH, j);
                if (s == 0) {
                    uint4* dh = (uint4*)(smc + SMB_H(nxt));
                    uint4* dl = (uint4*)(smc + SMB_L(nxt));
                    dh[t] = bhp0; dl[t] = blp0;
                    dh[t + 256] = bhp1; dl[t + 256] = blp1;
                    if (t < 64) { dh[t + 512] = bhp2; dl[t + 512] = blp2; }
                }
            }
        }
        __syncthreads();
    }

    // ---- epilogue: fragment -> g_raw ----
    int er = lane >> 2, ec = (lane & 3) * 2;
    #pragma unroll
    for (int mi = 0; mi < 2; mi++) {
        #pragma unroll
        for (int ni = 0; ni < 4; ni++) {
            int pix = pix0 + mb + 16 * mi + er;
            int o = nb + 8 * ni + ec;
            *(float2*)(g_raw + (size_t)pix * OO + o)       = make_float2(acc[mi][ni][0], acc[mi][ni][1]);
            *(float2*)(g_raw + (size_t)(pix + 8) * OO + o) = make_float2(acc[mi][ni][2], acc[mi][ni][3]);
        }
    }

    // ---- fused BN partial stats (fixed-order shfl tree + fixed warp order) ----
    float ps[8], pq[8];
    #pragma unroll
    for (int ni = 0; ni < 4; ni++) {
        float s0 = 0.f, q0 = 0.f, s1 = 0.f, q1 = 0.f;
        #pragma unroll
        for (int mi = 0; mi < 2; mi++) {
            float a0 = acc[mi][ni][0], a1 = acc[mi][ni][1];
            float a2 = acc[mi][ni][2], a3 = acc[mi][ni][3];
            s0 += a0 + a2;  q0 += a0 * a0 + a2 * a2;
            s1 += a1 + a3;  q1 += a1 * a1 + a3 * a3;
        }
        ps[2 * ni] = s0; pq[2 * ni] = q0;
        ps[2 * ni + 1] = s1; pq[2 * ni + 1] = q1;
    }
    #pragma unroll
    for (int off = 4; off <= 16; off <<= 1) {
        #pragma unroll
        for (int i = 0; i < 8; i++) {
            ps[i] += __shfl_xor_sync(0xFFFFFFFF, ps[i], off);
            pq[i] += __shfl_xor_sync(0xFFFFFFFF, pq[i], off);
        }
    }
    float* sms = (float*)smc;          // [8][32]
    float* smq = sms + 256;            // [8][32]
    if (lane < 4) {
        #pragma unroll
        for (int ni = 0; ni < 4; ni++) {
            int lo = 8 * ni + lane * 2;
            sms[w * 32 + lo]     = ps[2 * ni];
            sms[w * 32 + lo + 1] = ps[2 * ni + 1];
            smq[w * 32 + lo]     = pq[2 * ni];
            smq[w * 32 + lo + 1] = pq[2 * ni + 1];
        }
    }
    __syncthreads();
    if (t < 64) {
        int grp = t >> 5, wo = t & 31;
        float S = sms[(grp * 4 + 0) * 32 + wo] + sms[(grp * 4 + 1) * 32 + wo]
                + sms[(grp * 4 + 2) * 32 + wo] + sms[(grp * 4 + 3) * 32 + wo];
        float Q = smq[(grp * 4 + 0) * 32 + wo] + smq[(grp * 4 + 1) * 32 + wo]
                + smq[(grp * 4 + 2) * 32 + wo] + smq[(grp * 4 + 3) * 32 + wo];
        g_psum[blockIdx.x * OO + t] = S;
        g_psq[blockIdx.x * OO + t]  = Q;
    }
}

// ---------------- K3: finalize stats -> scale/shift ----------------
__global__ void k_stats2(const float* __restrict__ gamma, const float* __restrict__ beta) {
    __shared__ float ss[256], sq[256];
    int ch = blockIdx.x, t = threadIdx.x;
    ss[t] = g_psum[t * OO + ch] + g_psum[(t + 256) * OO + ch];
    sq[t] = g_psq[t * OO + ch]  + g_psq[(t + 256) * OO + ch];
    __syncthreads();
    for (int s = 128; s > 0; s >>= 1) {
        if (t < s) { ss[t] += ss[t + s]; sq[t] += sq[t + s]; }
        __syncthreads();
    }
    if (t == 0) {
        const float inv_n = 1.0f / (float)NPIX;
        float mean = ss[0] * inv_n;
        float var  = sq[0] * inv_n - mean * mean;
        float inv  = rsqrtf(var + 1e-5f);
        float sc   = gamma[ch] * inv;
        g_scale[ch] = sc;
        g_shift[ch] = beta[ch] - mean * sc;
        // conv bias cancels exactly inside batch-norm (per-channel constant)
    }
}

// ---------------- K4: BN + ReLU + NHWC->NCHW ----------------
__global__ void k_bnout(float* __restrict__ out) {
    __shared__ float s[64][65];
    __shared__ float scs[64], shs[64];
    int t = threadIdx.x;
    if (t < 64) { scs[t] = g_scale[t]; shs[t] = g_shift[t]; }
    __syncthreads();
    int pix0 = blockIdx.x * 64;
    int b = pix0 >> 14;
    int pl = pix0 & 16383;
    #pragma unroll
    for (int j = 0; j < 4; j++) {
        int idx = t + j * 256;
        int p = idx >> 4;      // 0..63 local pixel
        int q = idx & 15;      // float4 group of channels
        float4 v = *(const float4*)(g_raw + (size_t)(pix0 + p) * OO + q * 4);
        int c = q * 4;
        s[c + 0][p] = fmaxf(fmaf(v.x, scs[c + 0], shs[c + 0]), 0.0f);
        s[c + 1][p] = fmaxf(fmaf(v.y, scs[c + 1], shs[c + 1]), 0.0f);
        s[c + 2][p] = fmaxf(fmaf(v.z, scs[c + 2], shs[c + 2]), 0.0f);
        s[c + 3][p] = fmaxf(fmaf(v.w, scs[c + 3], shs[c + 3]), 0.0f);
    }
    __syncthreads();
    #pragma unroll
    for (int j = 0; j < 4; j++) {
        int idx = t + j * 256;
        int o = idx >> 4;
        int q = idx & 15;
        float4 r = make_float4(s[o][q * 4], s[o][q * 4 + 1], s[o][q * 4 + 2], s[o][q * 4 + 3]);
        *(float4*)(out + (size_t)(b * OO + o) * HWP + pl + q * 4) = r;
    }
}

// ---------------- launch ----------------
extern "C" void kernel_launch(void* const* d_in, const int* in_sizes, int n_in,
                              void* d_out, int out_size) {
    const float* x     = (const float*)d_in[0];
    const float* ow    = (const float*)d_in[1];
    const float* ob    = (const float*)d_in[2];
    const float* wt    = (const float*)d_in[3];
    // d_in[4] = bias: cancels exactly in batch norm, unused
    const float* gamma = (const float*)d_in[5];
    const float* beta  = (const float*)d_in[6];
    float* out = (float*)d_out;

    cudaFuncSetAttribute(k_offmma, cudaFuncAttributeMaxDynamicSharedMemorySize, OS_TOT);
    cudaFuncSetAttribute(k_main, cudaFuncAttributeMaxDynamicSharedMemorySize, SM_TOT);

    k_transpose<<<dim3(HWP / 32, CC / 32, BB), dim3(32, 8)>>>(x);
    k_prep<<<(9 * OO * CC + 255) / 256, 256>>>(wt, ow);
    k_offmma<<<NBLK, 256, OS_TOT>>>(ob);
    k_main<<<NBLK, 256, SM_TOT>>>();
    k_stats2<<<64, 256>>>(gamma, beta);
    k_bnout<<<NPIX / 64, 256>>>(out);
}

// round 16
// speedup vs baseline: 1.3901x; 1.0316x over previous
#include <cuda_runtime.h>
#include <cuda_bf16.h>
#include <cstdint>

// Problem constants (fixed shapes): B=4, C=64, H=W=128, O=64, K=3
#define BB 4
#define CC 64
#define HH 128
#define WW 128
#define OO 64
#define HWP (HH*WW)          // 16384
#define NPIX (BB*HWP)        // 65536
#define TILE 128             // pixels per block (one image row)
#define NBLK (NPIX / TILE)   // 512
#define BPITCH 144           // smem row pitch bytes (72 bf16): conflict-free ldmatrix

typedef unsigned long long u64;
typedef unsigned int u32;

// ---------------- scratch (static device globals; no allocation) ----------------
__device__ float  g_xh[(size_t)NPIX * CC];       // x in NHWC: [b][h][w][c]   16 MB
__device__ float4 g_smp[(size_t)9 * NPIX];       // per (tap, pixel): ys, xs, mask
__device__ float  g_raw[(size_t)NPIX * OO];      // pre-BN conv output, [pix][o]
__device__ __align__(16) unsigned char g_wth[9 * OO * BPITCH];   // main weight hi bf16 [tap][o][c]
__device__ __align__(16) unsigned char g_wtl[9 * OO * BPITCH];   // main weight lo bf16
__device__ __align__(16) unsigned char g_owth[9 * 32 * BPITCH];  // offset weight hi bf16 [tap][n][c]
__device__ __align__(16) unsigned char g_owtl[9 * 32 * BPITCH];  // offset weight lo bf16
__device__ float  g_psum[NBLK * OO];             // BN partial sums (per k_main block)
__device__ float  g_psq[NBLK * OO];              // BN partial sumsq
__device__ float  g_scale[OO];
__device__ float  g_shift[OO];

// ---------------- mma/ldmatrix/cp.async helpers (baseline PTX, works on sm_100) ----------------
__device__ __forceinline__ u32 smem_u32(const void* p) {
    u32 a;
    asm("{ .reg .u64 t; cvta.to.shared.u64 t, %1; cvt.u32.u64 %0, t; }" : "=r"(a) : "l"(p));
    return a;
}
__device__ __forceinline__ void ldsm4(u32* r, u32 addr) {
    asm volatile("ldmatrix.sync.aligned.m8n8.x4.shared.b16 {%0,%1,%2,%3}, [%4];"
        : "=r"(r[0]), "=r"(r[1]), "=r"(r[2]), "=r"(r[3]) : "r"(addr));
}
__device__ __forceinline__ void mma16816(float* c, const u32* a, u32 b0, u32 b1) {
    asm volatile(
        "mma.sync.aligned.m16n8k16.row.col.f32.bf16.bf16.f32 "
        "{%0,%1,%2,%3}, {%4,%5,%6,%7}, {%8,%9}, {%0,%1,%2,%3};"
        : "+f"(c[0]), "+f"(c[1]), "+f"(c[2]), "+f"(c[3])
        : "r"(a[0]), "r"(a[1]), "r"(a[2]), "r"(a[3]), "r"(b0), "r"(b1));
}
__device__ __forceinline__ void cpasync16(u32 smem, const void* g) {
    asm volatile("cp.async.cg.shared.global [%0], [%1], 16;" :: "r"(smem), "l"(g));
}
#define CPCOMMIT() asm volatile("cp.async.commit_group;" ::: "memory")
#define CPWAIT0()  asm volatile("cp.async.wait_group 0;" ::: "memory")

// split a float4 pair (8 ch) into bf16 hi/lo words and store to pitched rows
__device__ __forceinline__ void splitStore(float4 V0, float4 V1, char* rowH, char* rowL, int j) {
    float vf[8] = {V0.x, V0.y, V0.z, V0.w, V1.x, V1.y, V1.z, V1.w};
    u32 hp[4], lp[4];
    #pragma unroll
    for (int q = 0; q < 4; q++) {
        __nv_bfloat16 h0 = __float2bfloat16_rn(vf[2 * q]);
        __nv_bfloat16 h1 = __float2bfloat16_rn(vf[2 * q + 1]);
        float l0 = vf[2 * q]     - __bfloat162float(h0);
        float l1 = vf[2 * q + 1] - __bfloat162float(h1);
        __nv_bfloat162 hh; hh.x = h0; hh.y = h1;
        __nv_bfloat162 ll = __floats2bfloat162_rn(l0, l1);
        memcpy(&hp[q], &hh, 4);
        memcpy(&lp[q], &ll, 4);
    }
    *(uint2*)(rowH + 8 * j)      = make_uint2(hp[0], hp[1]);
    *(uint2*)(rowH + 64 + 8 * j) = make_uint2(hp[2], hp[3]);
    *(uint2*)(rowL + 8 * j)      = make_uint2(lp[0], lp[1]);
    *(uint2*)(rowL + 64 + 8 * j) = make_uint2(lp[2], lp[3]);
}

// k_main smem layout: double-buffered A hi/lo + B hi/lo
#define BUFSZ   55296
#define SMA_H(b) ((b) * BUFSZ + 0)
#define SMA_L(b) ((b) * BUFSZ + TILE * BPITCH)
#define SMB_H(b) ((b) * BUFSZ + 2 * TILE * BPITCH)
#define SMB_L(b) ((b) * BUFSZ + 2 * TILE * BPITCH + OO * BPITCH)
#define SM_TOT  (2 * BUFSZ)                                 // 110592

// k_offmma smem layout (single buffer)
#define OS_AH 0
#define OS_AL (TILE * BPITCH)            // 18432
#define OS_BH (2 * TILE * BPITCH)        // 36864
#define OS_BL (OS_BH + 32 * BPITCH)      // 41472
#define OS_TOT (OS_BL + 32 * BPITCH)     // 46080
#define CPITCH 34                        // epilogue C smem pitch (floats)

// ---------------- K0: NCHW -> NHWC transpose ----------------
__global__ void k_transpose(const float* __restrict__ x) {
    __shared__ float t[32][33];
    int b  = blockIdx.z;
    int c0 = blockIdx.y * 32;
    int p0 = blockIdx.x * 32;
    int tx = threadIdx.x, ty = threadIdx.y;
    #pragma unroll
    for (int j = 0; j < 4; j++) {
        int c = c0 + ty + j * 8;
        t[ty + j * 8][tx] = x[((size_t)(b * CC + c)) * HWP + p0 + tx];
    }
    __syncthreads();
    #pragma unroll
    for (int j = 0; j < 4; j++) {
        int p = p0 + ty + j * 8;
        g_xh[((size_t)(b * HWP + p)) * CC + c0 + tx] = t[tx][ty + j * 8];
    }
}

// ---------------- Kprep: weight relayouts (bf16 hi/lo split, pitched) ----------------
__global__ void k_prep(const float* __restrict__ wmain, const float* __restrict__ ow) {
    int i = blockIdx.x * 256 + threadIdx.x;
    if (i < 9 * OO * CC) {
        int k = i >> 12;           // tap
        int r = i & 4095;
        int o = r >> 6, c = r & 63;
        float w = wmain[o * 576 + c * 9 + k];
        __nv_bfloat16 hi = __float2bfloat16_rn(w);
        float lo = w - __bfloat162float(hi);
        size_t off = (size_t)k * OO * BPITCH + o * BPITCH + c * 2;
        *(__nv_bfloat16*)(g_wth + off) = hi;
        *(__nv_bfloat16*)(g_wtl + off) = __float2bfloat16_rn(lo);
    }
    if (i < 9 * 32 * CC) {         // offset conv weights: [tap][n(pad32)][c]
        int k = i >> 11;           // / 2048
        int r = i & 2047;
        int n = r >> 6, c = r & 63;
        float w = (n < 27) ? ow[n * 576 + c * 9 + k] : 0.0f;
        __nv_bfloat16 hi = __float2bfloat16_rn(w);
        float lo = w - __bfloat162float(hi);
        size_t off = (size_t)k * 32 * BPITCH + n * BPITCH + c * 2;
        *(__nv_bfloat16*)(g_owth + off) = hi;
        *(__nv_bfloat16*)(g_owtl + off) = __float2bfloat16_rn(lo);
    }
}

// ---------------- K1: offset conv via mma.sync -> sample coords + mask ----------------
__global__ __launch_bounds__(256, 3) void k_offmma(const float* __restrict__ ob) {
    extern __shared__ __align__(16) char smc[];
    u32 sb = smem_u32(smc);
    int t = threadIdx.x;
    int w = t >> 5, lane = t & 31;
    int pix0 = blockIdx.x * TILE;
    int b = pix0 >> 14;
    int h = (pix0 >> 7) & 127;
    const float* xb = g_xh + (size_t)(b << 14) * CC;

    int gg = t >> 3, j = t & 7;
    int mb = (w & 3) * 32;
    int nbh = (w >> 2) * 16;

    float acc[2][2][4];
    #pragma unroll
    for (int mi = 0; mi < 2; mi++)
        #pragma unroll
        for (int ni = 0; ni < 2; ni++)
            #pragma unroll
            for (int q = 0; q < 4; q++) acc[mi][ni][q] = 0.0f;

    u32 aAddr[2];
    #pragma unroll
    for (int mi = 0; mi < 2; mi++)
        aAddr[mi] = sb + OS_AH + (mb + 16 * mi + (lane & 15)) * BPITCH + (lane >> 4) * 16;
    u32 bAddr;
    {
        int nrow = nbh + ((lane >> 4) & 1) * 8 + (lane & 7);
        bAddr = sb + OS_BH + nrow * BPITCH + ((lane >> 3) & 1) * 16;
    }

    #pragma unroll 1
    for (int k = 0; k < 9; k++) {
        __syncthreads();
        {
            const uint4* sh = (const uint4*)(g_owth + (size_t)k * 32 * BPITCH);
            const uint4* sl = (const uint4*)(g_owtl + (size_t)k * 32 * BPITCH);
            uint4* dh = (uint4*)(smc + OS_BH);
            uint4* dl = (uint4*)(smc + OS_BL);
            if (t < 288 - 256) { dh[t + 256] = sh[t + 256]; dl[t + 256] = sl[t + 256]; }
            dh[t] = sh[t]; dl[t] = sl[t];
        }
        int y = h + k / 3 - 1;
        bool vy = ((unsigned)y < 128u);
        #pragma unroll 1
        for (int s = 0; s < 4; s++) {
            int p = gg * 4 + s;
            int x = p + (k % 3) - 1;
            bool v = vy && ((unsigned)x < 128u);
            float4 A0 = make_float4(0.f, 0.f, 0.f, 0.f), A1 = A0;
            if (v) {
                const float* src = xb + ((y << 7) + x) * CC + 4 * j;
                A0 = *(const float4*)src;
                A1 = *(const float4*)(src + 32);
            }
            splitStore(A0, A1, smc + OS_AH + p * BPITCH, smc + OS_AL + p * BPITCH, j);
        }
        __syncthreads();

        #pragma unroll
        for (int ks = 0; ks < 4; ks++) {
            u32 ah[2][4], al[2][4];
            #pragma unroll
            for (int mi = 0; mi < 2; mi++) {
                ldsm4(ah[mi], aAddr[mi] + ks * 32);
                ldsm4(al[mi], aAddr[mi] + ks * 32 + (OS_AL - OS_AH));
            }
            u32 bh[4], bl[4];
            ldsm4(bh, bAddr + ks * 32);
            ldsm4(bl, bAddr + ks * 32 + (OS_BL - OS_BH));
            #pragma unroll
            for (int mi = 0; mi < 2; mi++) {
                mma16816(acc[mi][0], ah[mi], bh[0], bh[1]);
                mma16816(acc[mi][0], ah[mi], bl[0], bl[1]);
                mma16816(acc[mi][0], al[mi], bh[0], bh[1]);
                mma16816(acc[mi][1], ah[mi], bh[2], bh[3]);
                mma16816(acc[mi][1], ah[mi], bl[2], bl[3]);
                mma16816(acc[mi][1], al[mi], bh[2], bh[3]);
            }
        }
    }
    __syncthreads();

    float* Csm = (float*)smc;
    int er = lane >> 2, ec = (lane & 3) * 2;
    #pragma unroll
    for (int mi = 0; mi < 2; mi++) {
        #pragma unroll
        for (int ni = 0; ni < 2; ni++) {
            int row = mb + 16 * mi + er;
            int col = nbh + 8 * ni + ec;
            *(float2*)&Csm[row * CPITCH + col]       = make_float2(acc[mi][ni][0], acc[mi][ni][1]);
            *(float2*)&Csm[(row + 8) * CPITCH + col] = make_float2(acc[mi][ni][2], acc[mi][ni][3]);
        }
    }
    __syncthreads();

    if (t < TILE) {
        int pix = pix0 + t;
        float c[27];
        #pragma unroll
        for (int i = 0; i < 27; i++) c[i] = Csm[t * CPITCH + i] + ob[i];
        #pragma unroll
        for (int k = 0; k < 9; k++) {
            float ys = (float)(h - 1 + k / 3) + c[2 * k];
            float xs = (float)(t - 1 + k % 3) + c[2 * k + 1];
            float mk = 1.0f / (1.0f + expf(-c[18 + k]));
            g_smp[(size_t)k * NPIX + pix] = make_float4(ys, xs, mk, 0.0f);
        }
    }
}

// ---------------- gather helpers for k_main ----------------
struct Pref {
    float4 a00, a01, a10, a11, b00, b01, b10, b11;
    float w00, w01, w10, w11;
};
__device__ __forceinline__ Pref issueGather(const float* xb, float4 sp, int j) {
    Pref P;
    float y0f = floorf(sp.x), x0f = floorf(sp.y);
    float fy = sp.x - y0f, fx = sp.y - x0f;
    int y0 = (int)y0f, x0 = (int)x0f;
    float m = sp.z, gy = 1.0f - fy, gx = 1.0f - fx;
    bool vy0 = ((unsigned)y0 < 128u), vy1 = ((unsigned)(y0 + 1) < 128u);
    bool vx0 = ((unsigned)x0 < 128u), vx1 = ((unsigned)(x0 + 1) < 128u);
    P.w00 = (vy0 && vx0) ? gy * gx * m : 0.0f;
    P.w01 = (vy0 && vx1) ? gy * fx * m : 0.0f;
    P.w10 = (vy1 && vx0) ? fy * gx * m : 0.0f;
    P.w11 = (vy1 && vx1) ? fy * fx * m : 0.0f;
    int r0 = (vy0 ? y0 : 0) << 7, r1 = (vy1 ? (y0 + 1) : 0) << 7;
    int cA = vx0 ? x0 : 0, cBx = vx1 ? (x0 + 1) : 0;
    const float* p00 = xb + (r0 + cA) * CC + 4 * j;
    const float* p01 = xb + (r0 + cBx) * CC + 4 * j;
    const float* p10 = xb + (r1 + cA) * CC + 4 * j;
    const float* p11 = xb + (r1 + cBx) * CC + 4 * j;
    P.a00 = *(const float4*)p00;        P.a01 = *(const float4*)p01;
    P.a10 = *(const float4*)p10;        P.a11 = *(const float4*)p11;
    P.b00 = *(const float4*)(p00 + 32); P.b01 = *(const float4*)(p01 + 32);
    P.b10 = *(const float4*)(p10 + 32); P.b11 = *(const float4*)(p11 + 32);
    return P;
}
__device__ __forceinline__ void retireGather(const Pref& P, char* rowH, char* rowL, int j) {
    float4 V0, V1;
    V0.x = fmaf(P.w00, P.a00.x, fmaf(P.w01, P.a01.x, fmaf(P.w10, P.a10.x, P.w11 * P.a11.x)));
    V0.y = fmaf(P.w00, P.a00.y, fmaf(P.w01, P.a01.y, fmaf(P.w10, P.a10.y, P.w11 * P.a11.y)));
    V0.z = fmaf(P.w00, P.a00.z, fmaf(P.w01, P.a01.z, fmaf(P.w10, P.a10.z, P.w11 * P.a11.z)));
    V0.w = fmaf(P.w00, P.a00.w, fmaf(P.w01, P.a01.w, fmaf(P.w10, P.a10.w, P.w11 * P.a11.w)));
    V1.x = fmaf(P.w00, P.b00.x, fmaf(P.w01, P.b01.x, fmaf(P.w10, P.b10.x, P.w11 * P.b11.x)));
    V1.y = fmaf(P.w00, P.b00.y, fmaf(P.w01, P.b01.y, fmaf(P.w10, P.b10.y, P.w11 * P.b11.y)));
    V1.z = fmaf(P.w00, P.b00.z, fmaf(P.w01, P.b01.z, fmaf(P.w10, P.b10.z, P.w11 * P.b11.z)));
    V1.w = fmaf(P.w00, P.b00.w, fmaf(P.w01, P.b01.w, fmaf(P.w10, P.b10.w, P.w11 * P.b11.w)));
    splitStore(V0, V1, rowH, rowL, j);
}

// ---------------- K2: pipelined (1 sync/tap) + sp depth-2 prefetch + cp.async B ----------------
__global__ __launch_bounds__(256, 2) void k_main() {
    extern __shared__ __align__(16) char smc[];
    u32 sb = smem_u32(smc);

    int t = threadIdx.x;
    int w = t >> 5, lane = t & 31;
    int pix0 = blockIdx.x * TILE;
    int b = pix0 >> 14;
    const float* xb = g_xh + (size_t)(b << 14) * CC;

    int gg = t >> 3;   // gather group 0..31 -> pixels 4gg..4gg+3
    int j  = t & 7;    // lane in group -> channels 4j..4j+3 and 32+4j..32+4j+3

    int mb = (w & 3) * 32;    // warp m base (pixels)
    int nb = (w >> 2) * 32;   // warp n base (outputs)

    float acc[2][4][4];
    #pragma unroll
    for (int mi = 0; mi < 2; mi++)
        #pragma unroll
        for (int ni = 0; ni < 4; ni++)
            #pragma unroll
            for (int q = 0; q < 4; q++) acc[mi][ni][q] = 0.0f;

    u32 aOff[2];
    #pragma unroll
    for (int mi = 0; mi < 2; mi++)
        aOff[mi] = (mb + 16 * mi + (lane & 15)) * BPITCH + (lane >> 4) * 16;
    u32 bOff[2];
    #pragma unroll
    for (int half = 0; half < 2; half++) {
        int nrow = nb + 16 * half + ((lane >> 4) & 1) * 8 + (lane & 7);
        bOff[half] = nrow * BPITCH + ((lane >> 3) & 1) * 16;
    }

    // ---- prologue: B0 copy + gather tap 0 into buf0 + prefetch sp for tap 1 ----
    float4 spN[4];
    {
        const uint4* sh = (const uint4*)g_wth;
        const uint4* sl = (const uint4*)g_wtl;
        uint4* dh = (uint4*)(smc + SMB_H(0));
        uint4* dl = (uint4*)(smc + SMB_L(0));
        dh[t] = sh[t]; dl[t] = sl[t];
        dh[t + 256] = sh[t + 256]; dl[t + 256] = sl[t + 256];
        if (t < 64) { dh[t + 512] = sh[t + 512]; dl[t + 512] = sl[t + 512]; }
        #pragma unroll 1
        for (int s = 0; s < 4; s++) {
            int p = gg * 4 + s;
            float4 sp = g_smp[pix0 + p];
            Pref P = issueGather(xb, sp, j);
            retireGather(P, smc + SMA_H(0) + p * BPITCH, smc + SMA_L(0) + p * BPITCH, j);
        }
        #pragma unroll
        for (int s = 0; s < 4; s++)
            spN[s] = g_smp[(size_t)1 * NPIX + pix0 + gg * 4 + s];
    }
    __syncthreads();

    // ---- pipelined main loop ----
    #pragma unroll 1
    for (int k = 0; k < 9; k++) {
        int cur = k & 1, nxt = cur ^ 1;
        bool pre = (k < 8);
        u32 baseAH = sb + SMA_H(cur), baseAL = sb + SMA_L(cur);
        u32 baseBH = sb + SMB_H(cur), baseBL = sb + SMB_L(cur);
        char* rowHb = smc + SMA_H(nxt);
        char* rowLb = smc + SMA_L(nxt);

        // --- async B prefetch for tap k+1 into next buffers ---
        if (pre) {
            const char* shh = (const char*)(g_wth + (size_t)(k + 1) * OO * BPITCH);
            const char* sll = (const char*)(g_wtl + (size_t)(k + 1) * OO * BPITCH);
            u32 dh = sb + SMB_H(nxt), dl = sb + SMB_L(nxt);
            #pragma unroll
            for (int i = 0; i < 3; i++) {
                int idx = t + i * 256;
                if (idx < 576) {
                    cpasync16(dh + idx * 16, shh + idx * 16);
                    cpasync16(dl + idx * 16, sll + idx * 16);
                }
            }
            CPCOMMIT();
        }

        #pragma unroll
        for (int s = 0; s < 4; s++) {
            int p = gg * 4 + s;
            // --- issue gather for tap k+1 using prefetched coords ---
            Pref P;
            if (pre) P = issueGather(xb, spN[s], j);
            // --- refill coord slot with tap k+2 (consumed next tap) ---
            if (k < 7) spN[s] = g_smp[(size_t)(k + 2) * NPIX + pix0 + p];

            // --- GEMM step ks = s on current buffers ---
            {
                u32 ah[2][4], al[2][4];
                #pragma unroll
                for (int mi = 0; mi < 2; mi++) {
                    ldsm4(ah[mi], baseAH + aOff[mi] + s * 32);
                    ldsm4(al[mi], baseAL + aOff[mi] + s * 32);
                }
                #pragma unroll
                for (int half = 0; half < 2; half++) {
                    u32 bh[4], bl[4];
                    ldsm4(bh, baseBH + bOff[half] + s * 32);
                    ldsm4(bl, baseBL + bOff[half] + s * 32);
                    #pragma unroll
                    for (int mi = 0; mi < 2; mi++) {
                        mma16816(acc[mi][2 * half],     ah[mi], bh[0], bh[1]);
                        mma16816(acc[mi][2 * half],     ah[mi], bl[0], bl[1]);
                        mma16816(acc[mi][2 * half],     al[mi], bh[0], bh[1]);
                        mma16816(acc[mi][2 * half + 1], ah[mi], bh[2], bh[3]);
                        mma16816(acc[mi][2 * half + 1], ah[mi], bl[2], bl[3]);
                        mma16816(acc[mi][2 * half + 1], al[mi], bh[2], bh[3]);
                    }
                }
            }

            // --- retire gather into next A buffers ---
            if (pre) retireGather(P, rowHb + p * BPITCH, rowLb + p * BPITCH, j);
        }
        if (pre) CPWAIT0();
        __syncthreads();
    }

    // ---- epilogue: fragment -> g_raw ----
    int er = lane >> 2, ec = (lane & 3) * 2;
    #pragma unroll
    for (int mi = 0; mi < 2; mi++) {
        #pragma unroll
        for (int ni = 0; ni < 4; ni++) {
            int pix = pix0 + mb + 16 * mi + er;
            int o = nb + 8 * ni + ec;
            *(float2*)(g_raw + (size_t)pix * OO + o)       = make_float2(acc[mi][ni][0], acc[mi][ni][1]);
            *(float2*)(g_raw + (size_t)(pix + 8) * OO + o) = make_float2(acc[mi][ni][2], acc[mi][ni][3]);
        }
    }

    // ---- fused BN partial stats (fixed-order shfl tree + fixed warp order) ----
    float ps[8], pq[8];
    #pragma unroll
    for (int ni = 0; ni < 4; ni++) {
        float s0 = 0.f, q0 = 0.f, s1 = 0.f, q1 = 0.f;
        #pragma unroll
        for (int mi = 0; mi < 2; mi++) {
            float a0 = acc[mi][ni][0], a1 = acc[mi][ni][1];
            float a2 = acc[mi][ni][2], a3 = acc[mi][ni][3];
            s0 += a0 + a2;  q0 += a0 * a0 + a2 * a2;
            s1 += a1 + a3;  q1 += a1 * a1 + a3 * a3;
        }
        ps[2 * ni] = s0; pq[2 * ni] = q0;
        ps[2 * ni + 1] = s1; pq[2 * ni + 1] = q1;
    }
    #pragma unroll
    for (int off = 4; off <= 16; off <<= 1) {
        #pragma unroll
        for (int i = 0; i < 8; i++) {
            ps[i] += __shfl_xor_sync(0xFFFFFFFF, ps[i], off);
            pq[i] += __shfl_xor_sync(0xFFFFFFFF, pq[i], off);
        }
    }
    float* sms = (float*)smc;          // [8][32]
    float* smq = sms + 256;            // [8][32]
    if (lane < 4) {
        #pragma unroll
        for (int ni = 0; ni < 4; ni++) {
            int lo = 8 * ni + lane * 2;
            sms[w * 32 + lo]     = ps[2 * ni];
            sms[w * 32 + lo + 1] = ps[2 * ni + 1];
            smq[w * 32 + lo]     = pq[2 * ni];
            smq[w * 32 + lo + 1] = pq[2 * ni + 1];
        }
    }
    __syncthreads();
    if (t < 64) {
        int grp = t >> 5, wo = t & 31;
        float S = sms[(grp * 4 + 0) * 32 + wo] + sms[(grp * 4 + 1) * 32 + wo]
                + sms[(grp * 4 + 2) * 32 + wo] + sms[(grp * 4 + 3) * 32 + wo];
        float Q = smq[(grp * 4 + 0) * 32 + wo] + smq[(grp * 4 + 1) * 32 + wo]
                + smq[(grp * 4 + 2) * 32 + wo] + smq[(grp * 4 + 3) * 32 + wo];
        g_psum[blockIdx.x * OO + t] = S;
        g_psq[blockIdx.x * OO + t]  = Q;
    }
}

// ---------------- K3: finalize stats -> scale/shift ----------------
__global__ void k_stats2(const float* __restrict__ gamma, const float* __restrict__ beta) {
    __shared__ float ss[256], sq[256];
    int ch = blockIdx.x, t = threadIdx.x;
    ss[t] = g_psum[t * OO + ch] + g_psum[(t + 256) * OO + ch];
    sq[t] = g_psq[t * OO + ch]  + g_psq[(t + 256) * OO + ch];
    __syncthreads();
    for (int s = 128; s > 0; s >>= 1) {
        if (t < s) { ss[t] += ss[t + s]; sq[t] += sq[t + s]; }
        __syncthreads();
    }
    if (t == 0) {
        const float inv_n = 1.0f / (float)NPIX;
        float mean = ss[0] * inv_n;
        float var  = sq[0] * inv_n - mean * mean;
        float inv  = rsqrtf(var + 1e-5f);
        float sc   = gamma[ch] * inv;
        g_scale[ch] = sc;
        g_shift[ch] = beta[ch] - mean * sc;
        // conv bias cancels exactly inside batch-norm (per-channel constant)
    }
}

// ---------------- K4: BN + ReLU + NHWC->NCHW ----------------
__global__ void k_bnout(float* __restrict__ out) {
    __shared__ float s[64][65];
    __shared__ float scs[64], shs[64];
    int t = threadIdx.x;
    if (t < 64) { scs[t] = g_scale[t]; shs[t] = g_shift[t]; }
    __syncthreads();
    int pix0 = blockIdx.x * 64;
    int b = pix0 >> 14;
    int pl = pix0 & 16383;
    #pragma unroll
    for (int j = 0; j < 4; j++) {
        int idx = t + j * 256;
        int p = idx >> 4;      // 0..63 local pixel
        int q = idx & 15;      // float4 group of channels
        float4 v = *(const float4*)(g_raw + (size_t)(pix0 + p) * OO + q * 4);
        int c = q * 4;
        s[c + 0][p] = fmaxf(fmaf(v.x, scs[c + 0], shs[c + 0]), 0.0f);
        s[c + 1][p] = fmaxf(fmaf(v.y, scs[c + 1], shs[c + 1]), 0.0f);
        s[c + 2][p] = fmaxf(fmaf(v.z, scs[c + 2], shs[c + 2]), 0.0f);
        s[c + 3][p] = fmaxf(fmaf(v.w, scs[c + 3], shs[c + 3]), 0.0f);
    }
    __syncthreads();
    #pragma unroll
    for (int j = 0; j < 4; j++) {
        int idx = t + j * 256;
        int o = idx >> 4;
        int q = idx & 15;
        float4 r = make_float4(s[o][q * 4], s[o][q * 4 + 1], s[o][q * 4 + 2], s[o][q * 4 + 3]);
        *(float4*)(out + (size_t)(b * OO + o) * HWP + pl + q * 4) = r;
    }
}

// ---------------- launch ----------------
extern "C" void kernel_launch(void* const* d_in, const int* in_sizes, int n_in,
                              void* d_out, int out_size) {
    const float* x     = (const float*)d_in[0];
    const float* ow    = (const float*)d_in[1];
    const float* ob    = (const float*)d_in[2];
    const float* wt    = (const float*)d_in[3];
    // d_in[4] = bias: cancels exactly in batch norm, unused
    const float* gamma = (const float*)d_in[5];
    const float* beta  = (const float*)d_in[6];
    float* out = (float*)d_out;

    cudaFuncSetAttribute(k_offmma, cudaFuncAttributeMaxDynamicSharedMemorySize, OS_TOT);
    cudaFuncSetAttribute(k_main, cudaFuncAttributeMaxDynamicSharedMemorySize, SM_TOT);

    k_transpose<<<dim3(HWP / 32, CC / 32, BB), dim3(32, 8)>>>(x);
    k_prep<<<(9 * OO * CC + 255) / 256, 256>>>(wt, ow);
    k_offmma<<<NBLK, 256, OS_TOT>>>(ob);
    k_main<<<NBLK, 256, SM_TOT>>>();
    k_stats2<<<64, 256>>>(gamma, beta);
    k_bnout<<<NPIX / 64, 256>>>(out);
}